// round 6
// baseline (speedup 1.0000x reference)
#include <cuda_runtime.h>

#define B_ 1024
#define T_ 512
#define K_ 48
#define NEG_ (-10000.0f)
#define START_ 46
#define STOP_ 47
#define NT 128
#define CHUNK 64

// scratch: v history, row t = 48 floats (~100.7 MB)
__device__ float g_v[(size_t)B_ * T_ * K_];

__device__ __forceinline__ float neg_inf() { return __int_as_float(0xff800000); }

// order-preserving float->uint map (no NaNs in our data)
__device__ __forceinline__ unsigned fmono(float x) {
    unsigned u = __float_as_uint(x);
    return (u & 0x80000000u) ? ~u : (u | 0x80000000u);
}
__device__ __forceinline__ float funmono(unsigned k) {
    return __uint_as_float((k & 0x80000000u) ? (k & 0x7fffffffu) : ~k);
}

__global__ __launch_bounds__(NT, 7)
void crf_kernel(const float* __restrict__ feats,
                const float* __restrict__ trans,
                const int* __restrict__ tags,
                float* __restrict__ out)
{
    const int b    = blockIdx.x;
    const int tid  = threadIdx.x;
    const int warp = tid >> 5;
    const int lane = tid & 31;
    const int grp  = warp >> 1;          // 0 = forward pair, 1 = viterbi pair
    const int wip  = warp & 1;           // warp-in-pair
    const int j    = wip * 32 + lane;    // state (valid < 48)
    const int js   = (j < K_) ? j : (K_ - 1);

    __shared__ float    shTr[K_ * K_];      // masked transitions (cold paths)
    __shared__ float    shA[2][K_];         // exp-domain forward (double buffered)
    __shared__ float    shV[2][K_];         // viterbi scores (double buffered)
    __shared__ float    shG[4];             // gold partials
    __shared__ unsigned shRF[2];            // fwd rescale max bits
    __shared__ float    shRZ[2];            // logZ reduce
    __shared__ float    shRed[2];           // terminal misc
    __shared__ float    shChunk[CHUNK * K_];

    const float* frow = feats + (size_t)b * (T_ * K_);
    const int*   trow = tags + b * T_;
    float* gvb = g_v + (size_t)b * T_ * K_;

    // ---- per-lane full transition row (masked): E for fwd, Tr for viterbi ----
    float T48[K_];
    if (grp == 1) {
        #pragma unroll
        for (int p = 0; p < K_; p++) {
            float tv = trans[js * K_ + p];
            if (js == START_) tv = NEG_;
            if (p == STOP_)   tv = NEG_;
            T48[p] = tv;
        }
        if (j < K_) {
            #pragma unroll
            for (int p = 0; p < K_; p++) shTr[j * K_ + p] = T48[p];
        }
    } else {
        #pragma unroll
        for (int p = 0; p < K_; p++) {
            float tv = trans[js * K_ + p];
            if (js == START_) tv = NEG_;
            if (p == STOP_)   tv = NEG_;
            T48[p] = __expf(tv);             // exp(-10000) -> exactly 0
        }
    }

    // ---- gold score ----
    float gp = 0.f;
    for (int t = tid; t < T_; t += NT) {
        int tg = trow[t];
        int pv = (t == 0) ? START_ : trow[t - 1];
        gp += frow[t * K_ + tg] + trans[tg * K_ + pv];
    }
    #pragma unroll
    for (int o = 16; o; o >>= 1) gp += __shfl_xor_sync(~0u, gp, o);
    if (lane == 0) shG[warp] = gp;

    if (tid < K_) {
        shA[0][tid] = (tid == START_) ? 1.0f : 0.0f;
        shV[0][tid] = (tid == START_) ? 0.0f : NEG_;
    }
    __syncthreads();
    float gold = shG[0] + shG[1] + shG[2] + shG[3]
               + trans[STOP_ * K_ + trow[T_ - 1]];

    if (grp == 0) {
        // ================= FORWARD PAIR (warps 0-1) =================
        int esum = 0;
        float scale = 1.0f;
        float emit_next = frow[js];
        #pragma unroll 8
        for (int t = 0; t < T_; t++) {
            float emit = emit_next;
            if (t < T_ - 1) emit_next = frow[(t + 1) * K_ + js];
            float eemit = __expf(emit);               // off critical path
            const float4* A4 = (const float4*)shA[t & 1];

            float s0, s1, s2, s3;
            {
                float4 a = A4[0];
                s0 = T48[0] * a.x; s1 = T48[1] * a.y;
                s2 = T48[2] * a.z; s3 = T48[3] * a.w;
            }
            #pragma unroll
            for (int q = 1; q < 12; q++) {
                float4 a = A4[q];
                s0 = fmaf(T48[4*q+0], a.x, s0);
                s1 = fmaf(T48[4*q+1], a.y, s1);
                s2 = fmaf(T48[4*q+2], a.z, s2);
                s3 = fmaf(T48[4*q+3], a.w, s3);
            }
            float sum = (s0 + s1) + (s2 + s3);
            float anew = eemit * (sum * scale);

            const bool resc = ((t & 7) == 7) && (t != T_ - 1);
            if (resc) {
                // anew >= 0 -> raw bits are order-preserving
                unsigned m = __reduce_max_sync(~0u, __float_as_uint(anew));
                if (lane == 0) shRF[wip] = m;
            }
            if (j < K_) shA[(t & 1) ^ 1][j] = anew;
            asm volatile("bar.sync 1, 64;" ::: "memory");
            if (resc) {
                unsigned mu = max(shRF[0], shRF[1]);
                int e = (int)((mu >> 23) & 255) - 127;
                scale = __uint_as_float((unsigned)(127 - e) << 23); // exact 2^-e
                esum += e;
            } else {
                scale = 1.0f;
            }
        }
        // final forward vector is shA[0]
        float contrib = 0.f;
        if (j < K_) contrib = shA[0][j] * __expf(shTr[STOP_ * K_ + j]);
        #pragma unroll
        for (int o = 16; o; o >>= 1) contrib += __shfl_xor_sync(~0u, contrib, o);
        if (lane == 0) shRZ[wip] = contrib;
        asm volatile("bar.sync 1, 64;" ::: "memory");
        if (tid == 0) {
            float Z = shRZ[0] + shRZ[1];
            double logZ = (double)esum * 0.6931471805599453 + (double)logf(Z);
            out[b] = (float)(logZ - (double)gold);
        }
    } else {
        // ================= VITERBI PAIR (warps 2-3) =================
        float emit_next = frow[js];
        #pragma unroll 4
        for (int t = 0; t < T_; t++) {
            float emit = emit_next;
            if (t < T_ - 1) emit_next = frow[(t + 1) * K_ + js];
            const float4* V4 = (const float4*)shV[t & 1];

            float m0, m1, m2, m3;
            {
                float4 v = V4[0];
                m0 = v.x + T48[0]; m1 = v.y + T48[1];
                m2 = v.z + T48[2]; m3 = v.w + T48[3];
            }
            #pragma unroll
            for (int q = 1; q < 12; q++) {
                float4 v = V4[q];
                m0 = fmaxf(m0, v.x + T48[4*q+0]);
                m1 = fmaxf(m1, v.y + T48[4*q+1]);
                m2 = fmaxf(m2, v.z + T48[4*q+2]);
                m3 = fmaxf(m3, v.w + T48[4*q+3]);
            }
            float vb = fmaxf(fmaxf(m0, m1), fmaxf(m2, m3));
            float vnew = vb + emit;      // bitwise-identical adds vs reference
            if (j < K_) {
                shV[(t & 1) ^ 1][j] = vnew;
                gvb[t * K_ + j] = vnew;  // stream v_t for backtrace
            }
            asm volatile("bar.sync 2, 64;" ::: "memory");
        }
    }
    __syncthreads();

    // ---- viterbi terminal: first-argmax over 48 (exact, jnp semantics) ----
    int tag = 0;
    if (warp == 0) {
        float x0 = shV[0][lane] + shTr[STOP_ * K_ + lane];
        float x1 = (lane < 16) ? shV[0][32 + lane] + shTr[STOP_ * K_ + 32 + lane]
                               : neg_inf();
        unsigned k0 = fmono(x0), k1 = fmono(x1);
        unsigned gm = __reduce_max_sync(~0u, (k0 > k1) ? k0 : k1);
        int cand = 1 << 30;
        if (k1 == gm) cand = 32 + lane;
        if (k0 == gm) cand = lane;       // lower p wins ties
        tag = __reduce_min_sync(~0u, cand);
        if (lane == 0) out[B_ + b] = funmono(gm);   // path_score
    }

    // ---- backtrace: chunked SMEM staging of v history, warp0 walks path ----
    float* pout = out + 2 * B_ + (size_t)b * T_;
    const int NCH = (T_ + CHUNK - 1) / CHUNK;        // 8
    for (int c = NCH - 1; c >= 0; c--) {
        int lo = c * CHUNK;
        int hi = lo + CHUNK;
        int base = lo - 1;
        int r0 = max(lo - 1, 0);
        int r1 = hi - 2;
        int n4 = (r1 - r0 + 1) * (K_ / 4);
        const float4* src4 = (const float4*)(gvb + r0 * K_);
        float4* dst4 = (float4*)(shChunk + (r0 - base) * K_);
        for (int i = tid; i < n4; i += NT) dst4[i] = src4[i];
        __syncthreads();
        if (warp == 0) {
            for (int t = hi - 1; t >= lo; t--) {
                if (lane == 0) pout[t] = (float)tag;
                float pv0, pv1;
                if (t == 0) {
                    pv0 = (lane == START_) ? 0.f : NEG_;
                    pv1 = (32 + lane == START_) ? 0.f : NEG_;
                } else {
                    const float* row = shChunk + (t - lo) * K_;   // row t-1
                    pv0 = row[lane];
                    pv1 = (lane < 16) ? row[32 + lane] : 0.f;
                }
                float x0 = pv0 + shTr[tag * K_ + lane];
                float x1 = (lane < 16) ? pv1 + shTr[tag * K_ + 32 + lane]
                                       : neg_inf();
                unsigned k0 = fmono(x0), k1 = fmono(x1);
                unsigned gm = __reduce_max_sync(~0u, (k0 > k1) ? k0 : k1);
                int cand = 1 << 30;
                if (k1 == gm) cand = 32 + lane;
                if (k0 == gm) cand = lane;
                tag = __reduce_min_sync(~0u, cand);
            }
        }
        __syncthreads();
    }
}

extern "C" void kernel_launch(void* const* d_in, const int* in_sizes, int n_in,
                              void* d_out, int out_size) {
    const float* feats = (const float*)d_in[0];
    const float* trans = (const float*)d_in[1];
    const int*   tags  = (const int*)d_in[2];
    crf_kernel<<<B_, NT>>>(feats, trans, tags, (float*)d_out);
}

// round 8
// speedup vs baseline: 1.7301x; 1.7301x over previous
#include <cuda_runtime.h>

#define B_ 1024
#define T_ 512
#define K_ 48
#define NEG_ (-10000.0f)
#define START_ 46
#define STOP_ 47
#define NT 96
#define CHUNK 64

// scratch: v history, row t = 48 floats (~100.7 MB)
__device__ __align__(16) float g_v[(size_t)B_ * T_ * K_];

__device__ __forceinline__ float neg_inf() { return __int_as_float(0xff800000); }

// order-preserving float->uint map (no NaNs in our data)
__device__ __forceinline__ unsigned fmono(float x) {
    unsigned u = __float_as_uint(x);
    return (u & 0x80000000u) ? ~u : (u | 0x80000000u);
}
__device__ __forceinline__ float funmono(unsigned k) {
    return __uint_as_float((k & 0x80000000u) ? (k & 0x7fffffffu) : ~k);
}

__global__ __launch_bounds__(NT, 7)
void crf_kernel(const float* __restrict__ feats,
                const float* __restrict__ trans,
                const int* __restrict__ tags,
                float* __restrict__ out)
{
    const int b    = blockIdx.x;
    const int tid  = threadIdx.x;
    const int warp = tid >> 5;          // 0..2
    const int lane = tid & 31;
    const int jg   = tid >> 2;          // output group 0..23
    const int s    = tid & 3;           // prev-slice 0..3 (p in [12s,12s+12))
    const int j0   = jg;                // row 0..23
    const int j1   = jg + 24;           // row 24..47

    __shared__ __align__(16) float shChunk[CHUNK * K_];  // backtrace staging (16B aligned!)
    __shared__ __align__(16) float shTr[K_ * K_];
    __shared__ __align__(16) float shA[2][K_];
    __shared__ __align__(16) float shV[2][K_];
    __shared__ float    shG[4];
    __shared__ unsigned shRF[4];
    __shared__ float    shRZ[4];

    const float* frow = feats + (size_t)b * (T_ * K_);
    const int*   trow = tags + b * T_;
    float* gvb = g_v + (size_t)b * T_ * K_;

    // ---- two masked transition rows per thread: E (exp) + Tr in registers ----
    float E0[12], E1[12], Tr0[12], Tr1[12];
    #pragma unroll
    for (int i = 0; i < 12; i++) {
        int p = 12 * s + i;
        float t0 = trans[j0 * K_ + p];             // j0<=23: never START_
        float t1 = trans[j1 * K_ + p];
        if (j1 == START_) t1 = NEG_;               // never INTO start
        if (p == STOP_) { t0 = NEG_; t1 = NEG_; }  // never OUT OF stop
        shTr[j0 * K_ + p] = t0;
        shTr[j1 * K_ + p] = t1;
        Tr0[i] = t0; Tr1[i] = t1;
        E0[i] = __expf(t0); E1[i] = __expf(t1);    // exp(-10000) -> exactly 0
    }

    // ---- gold score ----
    float gp = 0.f;
    for (int t = tid; t < T_; t += NT) {
        int tg = trow[t];
        int pv = (t == 0) ? START_ : trow[t - 1];
        gp += frow[t * K_ + tg] + trans[tg * K_ + pv];
    }
    #pragma unroll
    for (int o = 16; o; o >>= 1) gp += __shfl_xor_sync(~0u, gp, o);
    if (lane == 0) shG[warp] = gp;

    if (tid < K_) {
        shA[0][tid] = (tid == START_) ? 1.0f : 0.0f;   // exp(alpha_init)
        shV[0][tid] = (tid == START_) ? 0.0f : NEG_;
    }
    __syncthreads();
    float gold = shG[0] + shG[1] + shG[2]
               + trans[STOP_ * K_ + trow[T_ - 1]];

    // ---- main recurrence ----
    int esum = 0;
    float scale = 1.0f;
    float em0n = frow[j0], em1n = frow[j1];

    #pragma unroll 8
    for (int t = 0; t < T_; t++) {
        float em0 = em0n, em1 = em1n;
        if (t < T_ - 1) { em0n = frow[(t + 1) * K_ + j0]; em1n = frow[(t + 1) * K_ + j1]; }
        const int cur = t & 1, nxt = cur ^ 1;
        const float4* A4 = (const float4*)shA[cur];
        const float4* V4 = (const float4*)shV[cur];

        float s0a, s0b, s1a, s1b, m0a, m0b, m1a, m1b;
        {   // chunk 0
            float4 a = A4[3 * s + 0];
            float4 v = V4[3 * s + 0];
            s0a = E0[0] * a.x;            s0b = E0[1] * a.y;
            s0a = fmaf(E0[2], a.z, s0a);  s0b = fmaf(E0[3], a.w, s0b);
            s1a = E1[0] * a.x;            s1b = E1[1] * a.y;
            s1a = fmaf(E1[2], a.z, s1a);  s1b = fmaf(E1[3], a.w, s1b);
            m0a = v.x + Tr0[0];           m0b = v.y + Tr0[1];
            m0a = fmaxf(m0a, v.z + Tr0[2]); m0b = fmaxf(m0b, v.w + Tr0[3]);
            m1a = v.x + Tr1[0];           m1b = v.y + Tr1[1];
            m1a = fmaxf(m1a, v.z + Tr1[2]); m1b = fmaxf(m1b, v.w + Tr1[3]);
        }
        {   // chunk 1
            float4 a = A4[3 * s + 1];
            float4 v = V4[3 * s + 1];
            s0a = fmaf(E0[4], a.x, s0a);  s0b = fmaf(E0[5], a.y, s0b);
            s0a = fmaf(E0[6], a.z, s0a);  s0b = fmaf(E0[7], a.w, s0b);
            s1a = fmaf(E1[4], a.x, s1a);  s1b = fmaf(E1[5], a.y, s1b);
            s1a = fmaf(E1[6], a.z, s1a);  s1b = fmaf(E1[7], a.w, s1b);
            m0a = fmaxf(m0a, v.x + Tr0[4]); m0b = fmaxf(m0b, v.y + Tr0[5]);
            m0a = fmaxf(m0a, v.z + Tr0[6]); m0b = fmaxf(m0b, v.w + Tr0[7]);
            m1a = fmaxf(m1a, v.x + Tr1[4]); m1b = fmaxf(m1b, v.y + Tr1[5]);
            m1a = fmaxf(m1a, v.z + Tr1[6]); m1b = fmaxf(m1b, v.w + Tr1[7]);
        }
        {   // chunk 2
            float4 a = A4[3 * s + 2];
            float4 v = V4[3 * s + 2];
            s0a = fmaf(E0[8],  a.x, s0a); s0b = fmaf(E0[9],  a.y, s0b);
            s0a = fmaf(E0[10], a.z, s0a); s0b = fmaf(E0[11], a.w, s0b);
            s1a = fmaf(E1[8],  a.x, s1a); s1b = fmaf(E1[9],  a.y, s1b);
            s1a = fmaf(E1[10], a.z, s1a); s1b = fmaf(E1[11], a.w, s1b);
            m0a = fmaxf(m0a, v.x + Tr0[8]);  m0b = fmaxf(m0b, v.y + Tr0[9]);
            m0a = fmaxf(m0a, v.z + Tr0[10]); m0b = fmaxf(m0b, v.w + Tr0[11]);
            m1a = fmaxf(m1a, v.x + Tr1[8]);  m1b = fmaxf(m1b, v.y + Tr1[9]);
            m1a = fmaxf(m1a, v.z + Tr1[10]); m1b = fmaxf(m1b, v.w + Tr1[11]);
        }
        float sum0 = s0a + s0b, sum1 = s1a + s1b;
        float vb0 = fmaxf(m0a, m0b), vb1 = fmaxf(m1a, m1b);
        sum0 += __shfl_xor_sync(~0u, sum0, 1);
        sum1 += __shfl_xor_sync(~0u, sum1, 1);
        vb0 = fmaxf(vb0, __shfl_xor_sync(~0u, vb0, 1));
        vb1 = fmaxf(vb1, __shfl_xor_sync(~0u, vb1, 1));
        sum0 += __shfl_xor_sync(~0u, sum0, 2);
        sum1 += __shfl_xor_sync(~0u, sum1, 2);
        vb0 = fmaxf(vb0, __shfl_xor_sync(~0u, vb0, 2));
        vb1 = fmaxf(vb1, __shfl_xor_sync(~0u, vb1, 2));

        float anew0 = __expf(em0) * (sum0 * scale);
        float anew1 = __expf(em1) * (sum1 * scale);
        float vn0 = vb0 + em0;      // bitwise-identical adds vs reference
        float vn1 = vb1 + em1;

        const bool resc = ((t & 7) == 7) && (t != T_ - 1);
        if (resc) {
            // anew >= 0 -> raw bits order-preserving
            unsigned m = __reduce_max_sync(~0u,
                __float_as_uint(fmaxf(anew0, anew1)));
            if (lane == 0) shRF[warp] = m;
        }
        if (s == 0) {
            shA[nxt][j0] = anew0; shA[nxt][j1] = anew1;
            shV[nxt][j0] = vn0;   shV[nxt][j1] = vn1;
            gvb[t * K_ + j0] = vn0; gvb[t * K_ + j1] = vn1;
        }
        __syncthreads();
        if (resc) {
            unsigned mu = max(max(shRF[0], shRF[1]), shRF[2]);
            int e = (int)((mu >> 23) & 255) - 127;
            scale = __uint_as_float((unsigned)(127 - e) << 23);  // exact 2^-e
            esum += e;
        } else {
            scale = 1.0f;
        }
    }
    // final buffers are index 0

    // ---- logZ ----
    float contrib = 0.f;
    if (s == 0) {
        contrib = shA[0][j0] * __expf(shTr[STOP_ * K_ + j0])
                + shA[0][j1] * __expf(shTr[STOP_ * K_ + j1]);
    }
    #pragma unroll
    for (int o = 16; o; o >>= 1) contrib += __shfl_xor_sync(~0u, contrib, o);
    if (lane == 0) shRZ[warp] = contrib;
    __syncthreads();
    if (tid == 0) {
        float Z = shRZ[0] + shRZ[1] + shRZ[2];
        double logZ = (double)esum * 0.6931471805599453 + (double)logf(Z);
        out[b] = (float)(logZ - (double)gold);
    }

    // ---- viterbi terminal: first-argmax over 48 (exact, jnp semantics) ----
    int tag = 0;
    if (warp == 0) {
        float x0 = shV[0][lane] + shTr[STOP_ * K_ + lane];
        float x1 = (lane < 16) ? shV[0][32 + lane] + shTr[STOP_ * K_ + 32 + lane]
                               : neg_inf();
        unsigned k0 = fmono(x0), k1 = fmono(x1);
        unsigned gm = __reduce_max_sync(~0u, (k0 > k1) ? k0 : k1);
        int cand = 1 << 30;
        if (k1 == gm) cand = 32 + lane;
        if (k0 == gm) cand = lane;       // lower p wins ties
        tag = __reduce_min_sync(~0u, cand);
        if (lane == 0) out[B_ + b] = funmono(gm);   // path_score
    }

    // ---- backtrace: chunked SMEM staging of v history, warp0 walks path ----
    float* pout = out + 2 * B_ + (size_t)b * T_;
    const int NCH = (T_ + CHUNK - 1) / CHUNK;        // 8
    for (int c = NCH - 1; c >= 0; c--) {
        int lo = c * CHUNK;
        int hi = lo + CHUNK;
        int base = lo - 1;
        int r0 = max(lo - 1, 0);
        int r1 = hi - 2;
        int n4 = (r1 - r0 + 1) * (K_ / 4);
        const float4* src4 = (const float4*)(gvb + (size_t)r0 * K_);
        float4* dst4 = (float4*)(shChunk + (r0 - base) * K_);
        for (int i = tid; i < n4; i += NT) dst4[i] = src4[i];
        __syncthreads();
        if (warp == 0) {
            for (int t = hi - 1; t >= lo; t--) {
                if (lane == 0) pout[t] = (float)tag;
                float pv0, pv1;
                if (t == 0) {
                    pv0 = (lane == START_) ? 0.f : NEG_;
                    pv1 = (32 + lane == START_) ? 0.f : NEG_;
                } else {
                    const float* row = shChunk + (t - lo) * K_;   // row t-1
                    pv0 = row[lane];
                    pv1 = (lane < 16) ? row[32 + lane] : 0.f;
                }
                float x0 = pv0 + shTr[tag * K_ + lane];
                float x1 = (lane < 16) ? pv1 + shTr[tag * K_ + 32 + lane]
                                       : neg_inf();
                unsigned k0 = fmono(x0), k1 = fmono(x1);
                unsigned gm = __reduce_max_sync(~0u, (k0 > k1) ? k0 : k1);
                int cand = 1 << 30;
                if (k1 == gm) cand = 32 + lane;
                if (k0 == gm) cand = lane;
                tag = __reduce_min_sync(~0u, cand);
            }
        }
        __syncthreads();
    }
}

extern "C" void kernel_launch(void* const* d_in, const int* in_sizes, int n_in,
                              void* d_out, int out_size) {
    const float* feats = (const float*)d_in[0];
    const float* trans = (const float*)d_in[1];
    const int*   tags  = (const int*)d_in[2];
    crf_kernel<<<B_, NT>>>(feats, trans, tags, (float*)d_out);
}

// round 12
// speedup vs baseline: 1.7716x; 1.0240x over previous
#include <cuda_runtime.h>

#define B_ 1024
#define T_ 512
#define K_ 48
#define NEG_ (-10000.0f)
#define START_ 46
#define STOP_ 47
#define NT 96
#define CHUNK 64
#define NB 2

// scratch: v history, row t = 48 floats (~100.7 MB)
__device__ __align__(16) float g_v[(size_t)B_ * T_ * K_];

__device__ __forceinline__ float neg_inf() { return __int_as_float(0xff800000); }

// order-preserving float->uint map (no NaNs in our data)
__device__ __forceinline__ unsigned fmono(float x) {
    unsigned u = __float_as_uint(x);
    return (u & 0x80000000u) ? ~u : (u | 0x80000000u);
}
__device__ __forceinline__ float funmono(unsigned k) {
    return __uint_as_float((k & 0x80000000u) ? (k & 0x7fffffffu) : ~k);
}

// 48-wide dual-row forward+viterbi body over one batch's smem vectors
__device__ __forceinline__ void step_body(
    const float4* __restrict__ A4, const float4* __restrict__ V4, int s,
    const float (&E0)[12], const float (&E1)[12],
    const float (&Tr0)[12], const float (&Tr1)[12],
    float& sum0, float& sum1, float& vb0, float& vb1)
{
    float s0a, s0b, s1a, s1b, m0a, m0b, m1a, m1b;
    {
        float4 a = A4[3 * s + 0];
        float4 v = V4[3 * s + 0];
        s0a = E0[0] * a.x;            s0b = E0[1] * a.y;
        s0a = fmaf(E0[2], a.z, s0a);  s0b = fmaf(E0[3], a.w, s0b);
        s1a = E1[0] * a.x;            s1b = E1[1] * a.y;
        s1a = fmaf(E1[2], a.z, s1a);  s1b = fmaf(E1[3], a.w, s1b);
        m0a = v.x + Tr0[0];           m0b = v.y + Tr0[1];
        m0a = fmaxf(m0a, v.z + Tr0[2]); m0b = fmaxf(m0b, v.w + Tr0[3]);
        m1a = v.x + Tr1[0];           m1b = v.y + Tr1[1];
        m1a = fmaxf(m1a, v.z + Tr1[2]); m1b = fmaxf(m1b, v.w + Tr1[3]);
    }
    {
        float4 a = A4[3 * s + 1];
        float4 v = V4[3 * s + 1];
        s0a = fmaf(E0[4], a.x, s0a);  s0b = fmaf(E0[5], a.y, s0b);
        s0a = fmaf(E0[6], a.z, s0a);  s0b = fmaf(E0[7], a.w, s0b);
        s1a = fmaf(E1[4], a.x, s1a);  s1b = fmaf(E1[5], a.y, s1b);
        s1a = fmaf(E1[6], a.z, s1a);  s1b = fmaf(E1[7], a.w, s1b);
        m0a = fmaxf(m0a, v.x + Tr0[4]); m0b = fmaxf(m0b, v.y + Tr0[5]);
        m0a = fmaxf(m0a, v.z + Tr0[6]); m0b = fmaxf(m0b, v.w + Tr0[7]);
        m1a = fmaxf(m1a, v.x + Tr1[4]); m1b = fmaxf(m1b, v.y + Tr1[5]);
        m1a = fmaxf(m1a, v.z + Tr1[6]); m1b = fmaxf(m1b, v.w + Tr1[7]);
    }
    {
        float4 a = A4[3 * s + 2];
        float4 v = V4[3 * s + 2];
        s0a = fmaf(E0[8],  a.x, s0a); s0b = fmaf(E0[9],  a.y, s0b);
        s0a = fmaf(E0[10], a.z, s0a); s0b = fmaf(E0[11], a.w, s0b);
        s1a = fmaf(E1[8],  a.x, s1a); s1b = fmaf(E1[9],  a.y, s1b);
        s1a = fmaf(E1[10], a.z, s1a); s1b = fmaf(E1[11], a.w, s1b);
        m0a = fmaxf(m0a, v.x + Tr0[8]);  m0b = fmaxf(m0b, v.y + Tr0[9]);
        m0a = fmaxf(m0a, v.z + Tr0[10]); m0b = fmaxf(m0b, v.w + Tr0[11]);
        m1a = fmaxf(m1a, v.x + Tr1[8]);  m1b = fmaxf(m1b, v.y + Tr1[9]);
        m1a = fmaxf(m1a, v.z + Tr1[10]); m1b = fmaxf(m1b, v.w + Tr1[11]);
    }
    sum0 = s0a + s0b; sum1 = s1a + s1b;
    vb0 = fmaxf(m0a, m0b); vb1 = fmaxf(m1a, m1b);
}

__global__ __launch_bounds__(NT, 4)
void crf_kernel(const float* __restrict__ feats,
                const float* __restrict__ trans,
                const int* __restrict__ tags,
                float* __restrict__ out)
{
    const int bid  = blockIdx.x;        // handles batches 2*bid, 2*bid+1
    const int tid  = threadIdx.x;
    const int warp = tid >> 5;          // 0..2
    const int lane = tid & 31;
    const int jg   = tid >> 2;          // output group 0..23
    const int s    = tid & 3;           // prev-slice (p in [12s,12s+12))
    const int j0   = jg;
    const int j1   = jg + 24;

    __shared__ __align__(16) float shChunk[NB][CHUNK * K_];
    __shared__ __align__(16) float shTr[K_ * K_];
    __shared__ __align__(16) float shA[2][NB][K_];
    __shared__ __align__(16) float shV[2][NB][K_];
    __shared__ float    shG[NB][4];
    __shared__ unsigned shRF[NB][4];
    __shared__ float    shRZ[NB][4];

    const float* frow0 = feats + (size_t)(2 * bid + 0) * (T_ * K_);
    const float* frow1 = feats + (size_t)(2 * bid + 1) * (T_ * K_);
    float* gvb0 = g_v + (size_t)(2 * bid + 0) * T_ * K_;
    float* gvb1 = g_v + (size_t)(2 * bid + 1) * T_ * K_;

    // ---- two masked transition rows per thread (shared across both batches) ----
    float E0[12], E1[12], Tr0[12], Tr1[12];
    #pragma unroll
    for (int i = 0; i < 12; i++) {
        int p = 12 * s + i;
        float t0 = trans[j0 * K_ + p];             // j0<=23: never START_
        float t1 = trans[j1 * K_ + p];
        if (j1 == START_) t1 = NEG_;               // never INTO start
        if (p == STOP_) { t0 = NEG_; t1 = NEG_; }  // never OUT OF stop
        shTr[j0 * K_ + p] = t0;
        shTr[j1 * K_ + p] = t1;
        Tr0[i] = t0; Tr1[i] = t1;
        E0[i] = __expf(t0); E1[i] = __expf(t1);    // exp(-10000) -> exactly 0
    }

    // ---- gold scores (both batches) ----
    #pragma unroll
    for (int bb = 0; bb < NB; bb++) {
        const float* fr = bb ? frow1 : frow0;
        const int* trow = tags + (2 * bid + bb) * T_;
        float gp = 0.f;
        for (int t = tid; t < T_; t += NT) {
            int tg = trow[t];
            int pv = (t == 0) ? START_ : trow[t - 1];
            gp += fr[t * K_ + tg] + trans[tg * K_ + pv];
        }
        #pragma unroll
        for (int o = 16; o; o >>= 1) gp += __shfl_xor_sync(~0u, gp, o);
        if (lane == 0) shG[bb][warp] = gp;
    }

    if (tid < K_) {
        #pragma unroll
        for (int bb = 0; bb < NB; bb++) {
            shA[0][bb][tid] = (tid == START_) ? 1.0f : 0.0f;
            shV[0][bb][tid] = (tid == START_) ? 0.0f : NEG_;
        }
    }
    __syncthreads();
    float gold0 = shG[0][0] + shG[0][1] + shG[0][2]
                + trans[STOP_ * K_ + tags[(2 * bid + 0) * T_ + T_ - 1]];
    float gold1 = shG[1][0] + shG[1][1] + shG[1][2]
                + trans[STOP_ * K_ + tags[(2 * bid + 1) * T_ + T_ - 1]];

    // ---- main recurrence: two independent chains per thread ----
    int esum0 = 0, esum1 = 0;
    float scale0 = 1.0f, scale1 = 1.0f;
    float e0n_0 = frow0[j0], e1n_0 = frow0[j1];
    float e0n_1 = frow1[j0], e1n_1 = frow1[j1];

    #pragma unroll 8
    for (int t = 0; t < T_; t++) {
        float e0_0 = e0n_0, e1_0 = e1n_0, e0_1 = e0n_1, e1_1 = e1n_1;
        if (t < T_ - 1) {
            e0n_0 = frow0[(t + 1) * K_ + j0]; e1n_0 = frow0[(t + 1) * K_ + j1];
            e0n_1 = frow1[(t + 1) * K_ + j0]; e1n_1 = frow1[(t + 1) * K_ + j1];
        }
        const int cur = t & 1, nxt = cur ^ 1;

        float sum0_0, sum1_0, vb0_0, vb1_0;
        float sum0_1, sum1_1, vb0_1, vb1_1;
        step_body((const float4*)shA[cur][0], (const float4*)shV[cur][0], s,
                  E0, E1, Tr0, Tr1, sum0_0, sum1_0, vb0_0, vb1_0);
        step_body((const float4*)shA[cur][1], (const float4*)shV[cur][1], s,
                  E0, E1, Tr0, Tr1, sum0_1, sum1_1, vb0_1, vb1_1);

        sum0_0 += __shfl_xor_sync(~0u, sum0_0, 1);
        sum1_0 += __shfl_xor_sync(~0u, sum1_0, 1);
        sum0_1 += __shfl_xor_sync(~0u, sum0_1, 1);
        sum1_1 += __shfl_xor_sync(~0u, sum1_1, 1);
        vb0_0 = fmaxf(vb0_0, __shfl_xor_sync(~0u, vb0_0, 1));
        vb1_0 = fmaxf(vb1_0, __shfl_xor_sync(~0u, vb1_0, 1));
        vb0_1 = fmaxf(vb0_1, __shfl_xor_sync(~0u, vb0_1, 1));
        vb1_1 = fmaxf(vb1_1, __shfl_xor_sync(~0u, vb1_1, 1));
        sum0_0 += __shfl_xor_sync(~0u, sum0_0, 2);
        sum1_0 += __shfl_xor_sync(~0u, sum1_0, 2);
        sum0_1 += __shfl_xor_sync(~0u, sum0_1, 2);
        sum1_1 += __shfl_xor_sync(~0u, sum1_1, 2);
        vb0_0 = fmaxf(vb0_0, __shfl_xor_sync(~0u, vb0_0, 2));
        vb1_0 = fmaxf(vb1_0, __shfl_xor_sync(~0u, vb1_0, 2));
        vb0_1 = fmaxf(vb0_1, __shfl_xor_sync(~0u, vb0_1, 2));
        vb1_1 = fmaxf(vb1_1, __shfl_xor_sync(~0u, vb1_1, 2));

        float an0_0 = __expf(e0_0) * (sum0_0 * scale0);
        float an1_0 = __expf(e1_0) * (sum1_0 * scale0);
        float an0_1 = __expf(e0_1) * (sum0_1 * scale1);
        float an1_1 = __expf(e1_1) * (sum1_1 * scale1);
        float vn0_0 = vb0_0 + e0_0;   // bitwise-identical adds vs reference
        float vn1_0 = vb1_0 + e1_0;
        float vn0_1 = vb0_1 + e0_1;
        float vn1_1 = vb1_1 + e1_1;

        const bool resc = ((t & 7) == 7) && (t != T_ - 1);
        if (resc) {
            unsigned m0 = __reduce_max_sync(~0u, __float_as_uint(fmaxf(an0_0, an1_0)));
            unsigned m1 = __reduce_max_sync(~0u, __float_as_uint(fmaxf(an0_1, an1_1)));
            if (lane == 0) { shRF[0][warp] = m0; shRF[1][warp] = m1; }
        }
        if (s == 0) {
            shA[nxt][0][j0] = an0_0; shA[nxt][0][j1] = an1_0;
            shA[nxt][1][j0] = an0_1; shA[nxt][1][j1] = an1_1;
            shV[nxt][0][j0] = vn0_0; shV[nxt][0][j1] = vn1_0;
            shV[nxt][1][j0] = vn0_1; shV[nxt][1][j1] = vn1_1;
            gvb0[t * K_ + j0] = vn0_0; gvb0[t * K_ + j1] = vn1_0;
            gvb1[t * K_ + j0] = vn0_1; gvb1[t * K_ + j1] = vn1_1;
        }
        __syncthreads();
        if (resc) {
            unsigned mu0 = max(max(shRF[0][0], shRF[0][1]), shRF[0][2]);
            unsigned mu1 = max(max(shRF[1][0], shRF[1][1]), shRF[1][2]);
            int e0 = (int)((mu0 >> 23) & 255) - 127;
            int e1 = (int)((mu1 >> 23) & 255) - 127;
            scale0 = __uint_as_float((unsigned)(127 - e0) << 23);  // exact 2^-e
            scale1 = __uint_as_float((unsigned)(127 - e1) << 23);
            esum0 += e0; esum1 += e1;
        } else {
            scale0 = 1.0f; scale1 = 1.0f;
        }
    }
    // final buffers are index 0

    // ---- logZ for both batches ----
    #pragma unroll
    for (int bb = 0; bb < NB; bb++) {
        float contrib = 0.f;
        if (s == 0) {
            contrib = shA[0][bb][j0] * __expf(shTr[STOP_ * K_ + j0])
                    + shA[0][bb][j1] * __expf(shTr[STOP_ * K_ + j1]);
        }
        #pragma unroll
        for (int o = 16; o; o >>= 1) contrib += __shfl_xor_sync(~0u, contrib, o);
        if (lane == 0) shRZ[bb][warp] = contrib;
    }
    __syncthreads();
    if (tid == 0) {
        float Z0 = shRZ[0][0] + shRZ[0][1] + shRZ[0][2];
        float Z1 = shRZ[1][0] + shRZ[1][1] + shRZ[1][2];
        double lZ0 = (double)esum0 * 0.6931471805599453 + (double)logf(Z0);
        double lZ1 = (double)esum1 * 0.6931471805599453 + (double)logf(Z1);
        out[2 * bid + 0] = (float)(lZ0 - (double)gold0);
        out[2 * bid + 1] = (float)(lZ1 - (double)gold1);
    }

    // ---- viterbi terminal: warp bb handles batch bb (exact first-argmax) ----
    int tag = 0;
    if (warp < NB) {
        float x0 = shV[0][warp][lane] + shTr[STOP_ * K_ + lane];
        float x1 = (lane < 16) ? shV[0][warp][32 + lane] + shTr[STOP_ * K_ + 32 + lane]
                               : neg_inf();
        unsigned k0 = fmono(x0), k1 = fmono(x1);
        unsigned gm = __reduce_max_sync(~0u, (k0 > k1) ? k0 : k1);
        int cand = 1 << 30;
        if (k1 == gm) cand = 32 + lane;
        if (k0 == gm) cand = lane;       // lower p wins ties
        tag = __reduce_min_sync(~0u, cand);
        if (lane == 0) out[B_ + 2 * bid + warp] = funmono(gm);   // path_score
    }

    // ---- backtrace: stage both batches; warp0 walks b0, warp1 walks b1 ----
    const int NCH = (T_ + CHUNK - 1) / CHUNK;        // 8
    for (int c = NCH - 1; c >= 0; c--) {
        int lo = c * CHUNK;
        int hi = lo + CHUNK;
        int base = lo - 1;
        int r0 = max(lo - 1, 0);
        int r1 = hi - 2;
        int n4 = (r1 - r0 + 1) * (K_ / 4);
        {
            const float4* src0 = (const float4*)(gvb0 + (size_t)r0 * K_);
            const float4* src1 = (const float4*)(gvb1 + (size_t)r0 * K_);
            float4* dst0 = (float4*)(shChunk[0] + (r0 - base) * K_);
            float4* dst1 = (float4*)(shChunk[1] + (r0 - base) * K_);
            for (int i = tid; i < n4; i += NT) { dst0[i] = src0[i]; dst1[i] = src1[i]; }
        }
        __syncthreads();
        if (warp < NB) {
            float* pout = out + 2 * B_ + (size_t)(2 * bid + warp) * T_;
            const float* chunk = shChunk[warp];
            for (int t = hi - 1; t >= lo; t--) {
                if (lane == 0) pout[t] = (float)tag;
                float pv0, pv1;
                if (t == 0) {
                    pv0 = (lane == START_) ? 0.f : NEG_;
                    pv1 = (32 + lane == START_) ? 0.f : NEG_;
                } else {
                    const float* row = chunk + (t - lo) * K_;   // row t-1
                    pv0 = row[lane];
                    pv1 = (lane < 16) ? row[32 + lane] : 0.f;
                }
                float x0 = pv0 + shTr[tag * K_ + lane];
                float x1 = (lane < 16) ? pv1 + shTr[tag * K_ + 32 + lane]
                                       : neg_inf();
                unsigned k0 = fmono(x0), k1 = fmono(x1);
                unsigned gm = __reduce_max_sync(~0u, (k0 > k1) ? k0 : k1);
                int cand = 1 << 30;
                if (k1 == gm) cand = 32 + lane;
                if (k0 == gm) cand = lane;
                tag = __reduce_min_sync(~0u, cand);
            }
        }
        __syncthreads();
    }
}

extern "C" void kernel_launch(void* const* d_in, const int* in_sizes, int n_in,
                              void* d_out, int out_size) {
    const float* feats = (const float*)d_in[0];
    const float* trans = (const float*)d_in[1];
    const int*   tags  = (const int*)d_in[2];
    crf_kernel<<<B_ / NB, NT>>>(feats, trans, tags, (float*)d_out);
}

// round 14
// speedup vs baseline: 1.7888x; 1.0097x over previous
#include <cuda_runtime.h>

#define B_ 1024
#define T_ 512
#define K_ 48
#define NEG_ (-10000.0f)
#define START_ 46
#define STOP_ 47
#define NT 512
#define BPC 8    // batches per CTA (8 fwd warps + 8 vit warps)

// scratch: v history, row t = 48 floats (~100.7 MB)
__device__ __align__(16) float g_v[(size_t)B_ * T_ * K_];

__device__ __forceinline__ float neg_inf() { return __int_as_float(0xff800000); }

// order-preserving float->uint map (no NaNs in our data)
__device__ __forceinline__ unsigned fmono(float x) {
    unsigned u = __float_as_uint(x);
    return (u & 0x80000000u) ? ~u : (u | 0x80000000u);
}
__device__ __forceinline__ float funmono(unsigned k) {
    return __uint_as_float((k & 0x80000000u) ? (k & 0x7fffffffu) : ~k);
}

// ---- packed f32x2 helpers (sm_103a) ----
__device__ __forceinline__ unsigned long long pack2(float lo, float hi) {
    unsigned long long r;
    asm("mov.b64 %0, {%1, %2};" : "=l"(r) : "f"(lo), "f"(hi));
    return r;
}
__device__ __forceinline__ void unpack2(unsigned long long p, float& lo, float& hi) {
    asm("mov.b64 {%0, %1}, %2;" : "=f"(lo), "=f"(hi) : "l"(p));
}
__device__ __forceinline__ unsigned long long fmul2(unsigned long long a, unsigned long long b) {
    unsigned long long d;
    asm("mul.rn.f32x2 %0, %1, %2;" : "=l"(d) : "l"(a), "l"(b));
    return d;
}
__device__ __forceinline__ unsigned long long ffma2(unsigned long long a, unsigned long long b, unsigned long long c) {
    unsigned long long d;
    asm("fma.rn.f32x2 %0, %1, %2, %3;" : "=l"(d) : "l"(a), "l"(b), "l"(c));
    return d;
}
__device__ __forceinline__ unsigned long long fadd2(unsigned long long a, unsigned long long b) {
    unsigned long long d;
    asm("add.rn.f32x2 %0, %1, %2;" : "=l"(d) : "l"(a), "l"(b));
    return d;
}

__global__ __launch_bounds__(NT, 1)
void crf_kernel(const float* __restrict__ feats,
                const float* __restrict__ trans,
                const int* __restrict__ tags,
                float* __restrict__ out)
{
    const int bid  = blockIdx.x;
    const int tid  = threadIdx.x;
    const int warp = tid >> 5;
    const int lane = tid & 31;
    const bool is_vit = (warp >= BPC);
    const int bb   = is_vit ? warp - BPC : warp;
    const int gb   = bid * BPC + bb;
    const int s    = lane & 1;         // 24-wide half: p in [24s, 24s+24)
    const int rg   = lane >> 1;        // row group 0..15
    const int r0 = rg, r1 = rg + 16, r2 = rg + 32;

    __shared__ __align__(16) float shTr[K_ * K_];
    __shared__ __align__(16) float shA[2][BPC][K_];
    __shared__ __align__(16) float shV[2][BPC][K_];

    const float* frow = feats + (size_t)gb * (T_ * K_);
    float* gvb = g_v + (size_t)gb * (T_ * K_);

    // ---- 3 masked transition rows per lane, packed pairs in registers ----
    // fwd warps: exp(Tr) pairs.  vit warps: raw Tr pairs.
    unsigned long long C[3][12];
    {
        const int rows[3] = {r0, r1, r2};
        #pragma unroll
        for (int rr = 0; rr < 3; rr++) {
            int r = rows[rr];
            #pragma unroll
            for (int i = 0; i < 12; i++) {
                int p0 = 24 * s + 2 * i;
                int p1 = p0 + 1;
                float t0 = trans[r * K_ + p0];
                float t1 = trans[r * K_ + p1];
                if (r == START_) { t0 = NEG_; t1 = NEG_; }   // never INTO start
                if (p1 == STOP_)  t1 = NEG_;                 // never OUT OF stop (p0 is even, never 47)
                if (is_vit) C[rr][i] = pack2(t0, t1);
                else        C[rr][i] = pack2(__expf(t0), __expf(t1));  // exp(-1e4)->0
            }
        }
    }

    // warp BPC (first vit warp) publishes the full masked matrix for backtrace/terminal
    if (warp == BPC) {
        for (int idx = lane; idx < K_ * K_; idx += 32) {
            int r = idx / K_, p = idx % K_;
            float tv = trans[idx];
            if (r == START_) tv = NEG_;
            if (p == STOP_)  tv = NEG_;
            shTr[idx] = tv;
        }
    }
    if (tid < K_) {
        #pragma unroll
        for (int q = 0; q < BPC; q++) {
            shA[0][q][tid] = (tid == START_) ? 1.0f : 0.0f;   // exp-domain init
            shV[0][q][tid] = (tid == START_) ? 0.0f : NEG_;
        }
    }
    __syncthreads();   // only CTA-wide sync in the kernel

    if (!is_vit) {
        // ================= FORWARD WARP (one batch, self-contained) ============
        const int* trow = tags + gb * T_;
        float gp = 0.f;
        for (int t = lane; t < T_; t += 32) {
            int tg = trow[t];
            int pv = (t == 0) ? START_ : trow[t - 1];
            gp += frow[t * K_ + tg] + trans[tg * K_ + pv];
        }
        #pragma unroll
        for (int o = 16; o; o >>= 1) gp += __shfl_xor_sync(~0u, gp, o);
        // lane 0's gp is the emit+trans part of gold

        int esum = 0;
        float scale = 1.0f;
        float e0n = frow[r0], e1n = frow[r1], e2n = frow[r2];

        #pragma unroll 8
        for (int t = 0; t < T_; t++) {
            float e0 = e0n, e1 = e1n, e2 = e2n;
            if (t < T_ - 1) {
                e0n = frow[(t + 1) * K_ + r0];
                e1n = frow[(t + 1) * K_ + r1];
                e2n = frow[(t + 1) * K_ + r2];
            }
            const ulonglong2* A2 = (const ulonglong2*)&shA[t & 1][bb][24 * s];
            ulonglong2 a0 = A2[0], a1 = A2[1], a2 = A2[2],
                       a3 = A2[3], a4 = A2[4], a5 = A2[5];

            float sum0, sum1, sum2;
            #pragma unroll
            for (int rr = 0; rr < 3; rr++) {
                unsigned long long accA = fmul2(C[rr][0], a0.x);
                unsigned long long accB = fmul2(C[rr][1], a0.y);
                accA = ffma2(C[rr][2],  a1.x, accA);  accB = ffma2(C[rr][3],  a1.y, accB);
                accA = ffma2(C[rr][4],  a2.x, accA);  accB = ffma2(C[rr][5],  a2.y, accB);
                accA = ffma2(C[rr][6],  a3.x, accA);  accB = ffma2(C[rr][7],  a3.y, accB);
                accA = ffma2(C[rr][8],  a4.x, accA);  accB = ffma2(C[rr][9],  a4.y, accB);
                accA = ffma2(C[rr][10], a5.x, accA);  accB = ffma2(C[rr][11], a5.y, accB);
                unsigned long long ab = fadd2(accA, accB);
                float lo, hi; unpack2(ab, lo, hi);
                float v = lo + hi;
                if (rr == 0) sum0 = v; else if (rr == 1) sum1 = v; else sum2 = v;
            }
            sum0 += __shfl_xor_sync(~0u, sum0, 1);
            sum1 += __shfl_xor_sync(~0u, sum1, 1);
            sum2 += __shfl_xor_sync(~0u, sum2, 1);

            float an0 = __expf(e0) * (sum0 * scale);
            float an1 = __expf(e1) * (sum1 * scale);
            float an2 = __expf(e2) * (sum2 * scale);

            const bool resc = ((t & 7) == 7) && (t != T_ - 1);
            if (resc) {
                // an >= 0 -> raw bits order-preserving
                unsigned mu = __reduce_max_sync(~0u,
                    __float_as_uint(fmaxf(fmaxf(an0, an1), an2)));
                int e = (int)((mu >> 23) & 255) - 127;
                scale = __uint_as_float((unsigned)(127 - e) << 23);  // exact 2^-e
                esum += e;
            } else {
                scale = 1.0f;
            }
            float* dst = shA[(t & 1) ^ 1][bb];
            if (s == 0) { dst[r0] = an0; dst[r1] = an1; dst[r2] = an2; }
            __syncwarp();
        }
        // final alpha in shA[0][bb]
        float contrib = 0.f;
        if (s == 0) {
            contrib = shA[0][bb][r0] * __expf(shTr[STOP_ * K_ + r0])
                    + shA[0][bb][r1] * __expf(shTr[STOP_ * K_ + r1])
                    + shA[0][bb][r2] * __expf(shTr[STOP_ * K_ + r2]);
        }
        #pragma unroll
        for (int o = 16; o; o >>= 1) contrib += __shfl_xor_sync(~0u, contrib, o);
        if (lane == 0) {
            float goldv = gp + trans[STOP_ * K_ + trow[T_ - 1]];
            double logZ = (double)esum * 0.6931471805599453 + (double)logf(contrib);
            out[gb] = (float)(logZ - (double)goldv);
        }
    } else {
        // ================= VITERBI WARP (one batch, self-contained) ============
        float e0n = frow[r0], e1n = frow[r1], e2n = frow[r2];

        #pragma unroll 2
        for (int t = 0; t < T_; t++) {
            float e0 = e0n, e1 = e1n, e2 = e2n;
            if (t < T_ - 1) {
                e0n = frow[(t + 1) * K_ + r0];
                e1n = frow[(t + 1) * K_ + r1];
                e2n = frow[(t + 1) * K_ + r2];
            }
            const ulonglong2* V2 = (const ulonglong2*)&shV[t & 1][bb][24 * s];
            ulonglong2 v0 = V2[0], v1 = V2[1], v2 = V2[2],
                       v3 = V2[3], v4 = V2[4], v5 = V2[5];

            float vb0, vb1, vb2;
            #pragma unroll
            for (int rr = 0; rr < 3; rr++) {
                float m0, m1, m2, m3, lo, hi;
                unsigned long long p;
                // packed rn adds are bitwise-identical to scalar FADDs -> exact
                p = fadd2(v0.x, C[rr][0]);  unpack2(p, m0, m1);
                p = fadd2(v0.y, C[rr][1]);  unpack2(p, m2, m3);
                p = fadd2(v1.x, C[rr][2]);  unpack2(p, lo, hi);
                m0 = fmaxf(m0, lo); m1 = fmaxf(m1, hi);
                p = fadd2(v1.y, C[rr][3]);  unpack2(p, lo, hi);
                m2 = fmaxf(m2, lo); m3 = fmaxf(m3, hi);
                p = fadd2(v2.x, C[rr][4]);  unpack2(p, lo, hi);
                m0 = fmaxf(m0, lo); m1 = fmaxf(m1, hi);
                p = fadd2(v2.y, C[rr][5]);  unpack2(p, lo, hi);
                m2 = fmaxf(m2, lo); m3 = fmaxf(m3, hi);
                p = fadd2(v3.x, C[rr][6]);  unpack2(p, lo, hi);
                m0 = fmaxf(m0, lo); m1 = fmaxf(m1, hi);
                p = fadd2(v3.y, C[rr][7]);  unpack2(p, lo, hi);
                m2 = fmaxf(m2, lo); m3 = fmaxf(m3, hi);
                p = fadd2(v4.x, C[rr][8]);  unpack2(p, lo, hi);
                m0 = fmaxf(m0, lo); m1 = fmaxf(m1, hi);
                p = fadd2(v4.y, C[rr][9]);  unpack2(p, lo, hi);
                m2 = fmaxf(m2, lo); m3 = fmaxf(m3, hi);
                p = fadd2(v5.x, C[rr][10]); unpack2(p, lo, hi);
                m0 = fmaxf(m0, lo); m1 = fmaxf(m1, hi);
                p = fadd2(v5.y, C[rr][11]); unpack2(p, lo, hi);
                m2 = fmaxf(m2, lo); m3 = fmaxf(m3, hi);
                float v = fmaxf(fmaxf(m0, m1), fmaxf(m2, m3));
                if (rr == 0) vb0 = v; else if (rr == 1) vb1 = v; else vb2 = v;
            }
            vb0 = fmaxf(vb0, __shfl_xor_sync(~0u, vb0, 1));
            vb1 = fmaxf(vb1, __shfl_xor_sync(~0u, vb1, 1));
            vb2 = fmaxf(vb2, __shfl_xor_sync(~0u, vb2, 1));
            float vn0 = vb0 + e0;   // bitwise-identical adds vs reference
            float vn1 = vb1 + e1;
            float vn2 = vb2 + e2;

            float* dst = shV[(t & 1) ^ 1][bb];
            if (s == 0) {
                dst[r0] = vn0; dst[r1] = vn1; dst[r2] = vn2;
                gvb[t * K_ + r0] = vn0;       // stream v_t for backtrace
                gvb[t * K_ + r1] = vn1;
                gvb[t * K_ + r2] = vn2;
            }
            __syncwarp();
        }

        // ---- terminal: exact first-argmax over 48 (jnp semantics) ----
        int tag;
        {
            float x0 = shV[0][bb][lane] + shTr[STOP_ * K_ + lane];
            float x1 = (lane < 16) ? shV[0][bb][32 + lane] + shTr[STOP_ * K_ + 32 + lane]
                                   : neg_inf();
            unsigned k0 = fmono(x0), k1 = fmono(x1);
            unsigned gm = __reduce_max_sync(~0u, (k0 > k1) ? k0 : k1);
            int cand = 1 << 30;
            if (k1 == gm) cand = 32 + lane;
            if (k0 == gm) cand = lane;       // lower p wins ties
            tag = __reduce_min_sync(~0u, cand);
            if (lane == 0) out[B_ + gb] = funmono(gm);   // path_score
        }

        // ---- backtrace: depth-8 register-ring prefetch of v rows ----
        float* pout = out + 2 * B_ + (size_t)gb * T_;
        float rv0[8], rv1[8];
        #pragma unroll
        for (int d = 0; d < 8; d++) {
            int r = T_ - 2 - d;              // rows 510..503, slot r&7 = (6-d)&7
            rv0[(6 - d) & 7] = gvb[r * K_ + lane];
            rv1[(6 - d) & 7] = (lane < 16) ? gvb[r * K_ + 32 + lane] : 0.f;
        }
        for (int tb = T_ - 1; tb >= 7; tb -= 8) {   // tb ≡ 7 (mod 8)
            #pragma unroll
            for (int d = 0; d < 8; d++) {
                int t = tb - d;
                if (lane == 0) pout[t] = (float)tag;
                if (t > 0) {
                    const int slot = (6 - d) & 7;   // == (t-1)&7
                    float x0 = rv0[slot] + shTr[tag * K_ + lane];
                    float x1 = (lane < 16) ? rv1[slot] + shTr[tag * K_ + 32 + lane]
                                           : neg_inf();
                    unsigned k0 = fmono(x0), k1 = fmono(x1);
                    unsigned gm = __reduce_max_sync(~0u, (k0 > k1) ? k0 : k1);
                    int cand = 1 << 30;
                    if (k1 == gm) cand = 32 + lane;
                    if (k0 == gm) cand = lane;
                    tag = __reduce_min_sync(~0u, cand);
                    int pr = t - 9;
                    if (pr >= 0) {
                        rv0[slot] = gvb[pr * K_ + lane];
                        rv1[slot] = (lane < 16) ? gvb[pr * K_ + 32 + lane] : 0.f;
                    }
                }
            }
        }
    }
}

extern "C" void kernel_launch(void* const* d_in, const int* in_sizes, int n_in,
                              void* d_out, int out_size) {
    const float* feats = (const float*)d_in[0];
    const float* trans = (const float*)d_in[1];
    const int*   tags  = (const int*)d_in[2];
    crf_kernel<<<B_ / BPC, NT>>>(feats, trans, tags, (float*)d_out);
}

// round 16
// speedup vs baseline: 2.4329x; 1.3601x over previous
#include <cuda_runtime.h>

#define B_ 1024
#define T_ 512
#define K_ 48
#define NEG_ (-10000.0f)
#define START_ 46
#define STOP_ 47
#define NT 64   // warp0 = forward, warp1 = viterbi; 1 batch per CTA

// scratch: v history, row t = 48 floats (~100.7 MB)
__device__ __align__(16) float g_v[(size_t)B_ * T_ * K_];

__device__ __forceinline__ float neg_inf() { return __int_as_float(0xff800000); }

// order-preserving float->uint map (no NaNs in our data)
__device__ __forceinline__ unsigned fmono(float x) {
    unsigned u = __float_as_uint(x);
    return (u & 0x80000000u) ? ~u : (u | 0x80000000u);
}
__device__ __forceinline__ float funmono(unsigned k) {
    return __uint_as_float((k & 0x80000000u) ? (k & 0x7fffffffu) : ~k);
}

// ---- packed f32x2 helpers (sm_103a) ----
__device__ __forceinline__ unsigned long long pack2(float lo, float hi) {
    unsigned long long r;
    asm("mov.b64 %0, {%1, %2};" : "=l"(r) : "f"(lo), "f"(hi));
    return r;
}
__device__ __forceinline__ void unpack2(unsigned long long p, float& lo, float& hi) {
    asm("mov.b64 {%0, %1}, %2;" : "=f"(lo), "=f"(hi) : "l"(p));
}
__device__ __forceinline__ unsigned long long fmul2(unsigned long long a, unsigned long long b) {
    unsigned long long d;
    asm("mul.rn.f32x2 %0, %1, %2;" : "=l"(d) : "l"(a), "l"(b));
    return d;
}
__device__ __forceinline__ unsigned long long ffma2(unsigned long long a, unsigned long long b, unsigned long long c) {
    unsigned long long d;
    asm("fma.rn.f32x2 %0, %1, %2, %3;" : "=l"(d) : "l"(a), "l"(b), "l"(c));
    return d;
}
__device__ __forceinline__ unsigned long long fadd2(unsigned long long a, unsigned long long b) {
    unsigned long long d;
    asm("add.rn.f32x2 %0, %1, %2;" : "=l"(d) : "l"(a), "l"(b));
    return d;
}

__global__ __launch_bounds__(NT, 8)
void crf_kernel(const float* __restrict__ feats,
                const float* __restrict__ trans,
                const int* __restrict__ tags,
                float* __restrict__ out)
{
    const int gb   = blockIdx.x;        // one batch per CTA
    const int tid  = threadIdx.x;
    const int warp = tid >> 5;          // 0 = fwd, 1 = vit
    const int lane = tid & 31;
    const bool is_vit = (warp == 1);
    const int s    = lane & 1;          // 24-wide half: p in [24s, 24s+24)
    const int rg   = lane >> 1;         // row group 0..15
    const int r0 = rg, r1 = rg + 16, r2 = rg + 32;

    __shared__ __align__(16) float shTr[K_ * K_];
    __shared__ __align__(16) float shA[2][K_];
    __shared__ __align__(16) float shV[2][K_];

    const float* frow = feats + (size_t)gb * (T_ * K_);
    float* gvb = g_v + (size_t)gb * (T_ * K_);

    // ---- full masked matrix to smem (both warps cooperate) ----
    for (int idx = tid; idx < K_ * K_; idx += NT) {
        int r = idx / K_, p = idx % K_;
        float tv = trans[idx];
        if (r == START_) tv = NEG_;   // never INTO start
        if (p == STOP_)  tv = NEG_;   // never OUT OF stop
        shTr[idx] = tv;
    }
    if (tid < K_) {
        shA[0][tid] = (tid == START_) ? 1.0f : 0.0f;   // exp-domain init
        shV[0][tid] = (tid == START_) ? 0.0f : NEG_;
    }
    __syncthreads();   // only CTA-wide sync in the kernel

    // ---- 3 masked transition rows per lane, packed pairs in registers ----
    // fwd warp: exp(Tr) pairs.  vit warp: raw Tr pairs.
    unsigned long long C[3][12];
    {
        const int rows[3] = {r0, r1, r2};
        #pragma unroll
        for (int rr = 0; rr < 3; rr++) {
            const float* row = shTr + rows[rr] * K_;
            #pragma unroll
            for (int i = 0; i < 12; i++) {
                float t0 = row[24 * s + 2 * i];
                float t1 = row[24 * s + 2 * i + 1];
                if (is_vit) C[rr][i] = pack2(t0, t1);
                else        C[rr][i] = pack2(__expf(t0), __expf(t1));  // exp(-1e4)->0
            }
        }
    }

    if (!is_vit) {
        // ================= FORWARD WARP =================
        const int* trow = tags + gb * T_;
        float gp = 0.f;
        for (int t = lane; t < T_; t += 32) {
            int tg = trow[t];
            int pv = (t == 0) ? START_ : trow[t - 1];
            gp += frow[t * K_ + tg] + trans[tg * K_ + pv];
        }
        #pragma unroll
        for (int o = 16; o; o >>= 1) gp += __shfl_xor_sync(~0u, gp, o);

        int esum = 0;
        float scale = 1.0f;
        float e0n = frow[r0], e1n = frow[r1], e2n = frow[r2];

        #pragma unroll 8
        for (int t = 0; t < T_; t++) {
            float e0 = e0n, e1 = e1n, e2 = e2n;
            if (t < T_ - 1) {
                e0n = frow[(t + 1) * K_ + r0];
                e1n = frow[(t + 1) * K_ + r1];
                e2n = frow[(t + 1) * K_ + r2];
            }
            const ulonglong2* A2 = (const ulonglong2*)&shA[t & 1][24 * s];
            ulonglong2 a0 = A2[0], a1 = A2[1], a2 = A2[2],
                       a3 = A2[3], a4 = A2[4], a5 = A2[5];

            float sum0, sum1, sum2;
            #pragma unroll
            for (int rr = 0; rr < 3; rr++) {
                unsigned long long accA = fmul2(C[rr][0], a0.x);
                unsigned long long accB = fmul2(C[rr][1], a0.y);
                accA = ffma2(C[rr][2],  a1.x, accA);  accB = ffma2(C[rr][3],  a1.y, accB);
                accA = ffma2(C[rr][4],  a2.x, accA);  accB = ffma2(C[rr][5],  a2.y, accB);
                accA = ffma2(C[rr][6],  a3.x, accA);  accB = ffma2(C[rr][7],  a3.y, accB);
                accA = ffma2(C[rr][8],  a4.x, accA);  accB = ffma2(C[rr][9],  a4.y, accB);
                accA = ffma2(C[rr][10], a5.x, accA);  accB = ffma2(C[rr][11], a5.y, accB);
                unsigned long long ab = fadd2(accA, accB);
                float lo, hi; unpack2(ab, lo, hi);
                float v = lo + hi;
                if (rr == 0) sum0 = v; else if (rr == 1) sum1 = v; else sum2 = v;
            }
            sum0 += __shfl_xor_sync(~0u, sum0, 1);
            sum1 += __shfl_xor_sync(~0u, sum1, 1);
            sum2 += __shfl_xor_sync(~0u, sum2, 1);

            float an0 = __expf(e0) * (sum0 * scale);
            float an1 = __expf(e1) * (sum1 * scale);
            float an2 = __expf(e2) * (sum2 * scale);

            const bool resc = ((t & 7) == 7) && (t != T_ - 1);
            if (resc) {
                // an >= 0 -> raw bits order-preserving
                unsigned mu = __reduce_max_sync(~0u,
                    __float_as_uint(fmaxf(fmaxf(an0, an1), an2)));
                int e = (int)((mu >> 23) & 255) - 127;
                scale = __uint_as_float((unsigned)(127 - e) << 23);  // exact 2^-e
                esum += e;
            } else {
                scale = 1.0f;
            }
            float* dst = shA[(t & 1) ^ 1];
            if (s == 0) { dst[r0] = an0; dst[r1] = an1; dst[r2] = an2; }
            __syncwarp();
        }
        // final alpha in shA[0]
        float contrib = 0.f;
        if (s == 0) {
            contrib = shA[0][r0] * __expf(shTr[STOP_ * K_ + r0])
                    + shA[0][r1] * __expf(shTr[STOP_ * K_ + r1])
                    + shA[0][r2] * __expf(shTr[STOP_ * K_ + r2]);
        }
        #pragma unroll
        for (int o = 16; o; o >>= 1) contrib += __shfl_xor_sync(~0u, contrib, o);
        if (lane == 0) {
            float goldv = gp + trans[STOP_ * K_ + trow[T_ - 1]];
            double logZ = (double)esum * 0.6931471805599453 + (double)logf(contrib);
            out[gb] = (float)(logZ - (double)goldv);
        }
    } else {
        // ================= VITERBI WARP =================
        float e0n = frow[r0], e1n = frow[r1], e2n = frow[r2];

        #pragma unroll 4
        for (int t = 0; t < T_; t++) {
            float e0 = e0n, e1 = e1n, e2 = e2n;
            if (t < T_ - 1) {
                e0n = frow[(t + 1) * K_ + r0];
                e1n = frow[(t + 1) * K_ + r1];
                e2n = frow[(t + 1) * K_ + r2];
            }
            const ulonglong2* V2 = (const ulonglong2*)&shV[t & 1][24 * s];
            ulonglong2 v0 = V2[0], v1 = V2[1], v2 = V2[2],
                       v3 = V2[3], v4 = V2[4], v5 = V2[5];

            float vb0, vb1, vb2;
            #pragma unroll
            for (int rr = 0; rr < 3; rr++) {
                float m0, m1, m2, m3, lo, hi;
                unsigned long long p;
                // packed rn adds are bitwise-identical to scalar FADDs -> exact
                p = fadd2(v0.x, C[rr][0]);  unpack2(p, m0, m1);
                p = fadd2(v0.y, C[rr][1]);  unpack2(p, m2, m3);
                p = fadd2(v1.x, C[rr][2]);  unpack2(p, lo, hi);
                m0 = fmaxf(m0, lo); m1 = fmaxf(m1, hi);
                p = fadd2(v1.y, C[rr][3]);  unpack2(p, lo, hi);
                m2 = fmaxf(m2, lo); m3 = fmaxf(m3, hi);
                p = fadd2(v2.x, C[rr][4]);  unpack2(p, lo, hi);
                m0 = fmaxf(m0, lo); m1 = fmaxf(m1, hi);
                p = fadd2(v2.y, C[rr][5]);  unpack2(p, lo, hi);
                m2 = fmaxf(m2, lo); m3 = fmaxf(m3, hi);
                p = fadd2(v3.x, C[rr][6]);  unpack2(p, lo, hi);
                m0 = fmaxf(m0, lo); m1 = fmaxf(m1, hi);
                p = fadd2(v3.y, C[rr][7]);  unpack2(p, lo, hi);
                m2 = fmaxf(m2, lo); m3 = fmaxf(m3, hi);
                p = fadd2(v4.x, C[rr][8]);  unpack2(p, lo, hi);
                m0 = fmaxf(m0, lo); m1 = fmaxf(m1, hi);
                p = fadd2(v4.y, C[rr][9]);  unpack2(p, lo, hi);
                m2 = fmaxf(m2, lo); m3 = fmaxf(m3, hi);
                p = fadd2(v5.x, C[rr][10]); unpack2(p, lo, hi);
                m0 = fmaxf(m0, lo); m1 = fmaxf(m1, hi);
                p = fadd2(v5.y, C[rr][11]); unpack2(p, lo, hi);
                m2 = fmaxf(m2, lo); m3 = fmaxf(m3, hi);
                float v = fmaxf(fmaxf(m0, m1), fmaxf(m2, m3));
                if (rr == 0) vb0 = v; else if (rr == 1) vb1 = v; else vb2 = v;
            }
            vb0 = fmaxf(vb0, __shfl_xor_sync(~0u, vb0, 1));
            vb1 = fmaxf(vb1, __shfl_xor_sync(~0u, vb1, 1));
            vb2 = fmaxf(vb2, __shfl_xor_sync(~0u, vb2, 1));
            float vn0 = vb0 + e0;   // bitwise-identical adds vs reference
            float vn1 = vb1 + e1;
            float vn2 = vb2 + e2;

            float* dst = shV[(t & 1) ^ 1];
            if (s == 0) {
                dst[r0] = vn0; dst[r1] = vn1; dst[r2] = vn2;
                gvb[t * K_ + r0] = vn0;       // stream v_t for backtrace
                gvb[t * K_ + r1] = vn1;
                gvb[t * K_ + r2] = vn2;
            }
            __syncwarp();
        }

        // ---- terminal: exact first-argmax over 48 (jnp semantics) ----
        int tag;
        {
            float x0 = shV[0][lane] + shTr[STOP_ * K_ + lane];
            float x1 = (lane < 16) ? shV[0][32 + lane] + shTr[STOP_ * K_ + 32 + lane]
                                   : neg_inf();
            unsigned k0 = fmono(x0), k1 = fmono(x1);
            unsigned gm = __reduce_max_sync(~0u, (k0 > k1) ? k0 : k1);
            int cand = 1 << 30;
            if (k1 == gm) cand = 32 + lane;
            if (k0 == gm) cand = lane;       // lower p wins ties
            tag = __reduce_min_sync(~0u, cand);
            if (lane == 0) out[B_ + gb] = funmono(gm);   // path_score
        }

        // ---- backtrace: depth-8 register-ring prefetch of v rows ----
        float* pout = out + 2 * B_ + (size_t)gb * T_;
        float rv0[8], rv1[8];
        #pragma unroll
        for (int d = 0; d < 8; d++) {
            int r = T_ - 2 - d;              // rows 510..503, slot r&7 = (6-d)&7
            rv0[(6 - d) & 7] = gvb[r * K_ + lane];
            rv1[(6 - d) & 7] = (lane < 16) ? gvb[r * K_ + 32 + lane] : 0.f;
        }
        for (int tb = T_ - 1; tb >= 7; tb -= 8) {   // tb ≡ 7 (mod 8)
            #pragma unroll
            for (int d = 0; d < 8; d++) {
                int t = tb - d;
                if (lane == 0) pout[t] = (float)tag;
                if (t > 0) {
                    const int slot = (6 - d) & 7;   // == (t-1)&7
                    float x0 = rv0[slot] + shTr[tag * K_ + lane];
                    float x1 = (lane < 16) ? rv1[slot] + shTr[tag * K_ + 32 + lane]
                                           : neg_inf();
                    unsigned k0 = fmono(x0), k1 = fmono(x1);
                    unsigned gm = __reduce_max_sync(~0u, (k0 > k1) ? k0 : k1);
                    int cand = 1 << 30;
                    if (k1 == gm) cand = 32 + lane;
                    if (k0 == gm) cand = lane;
                    tag = __reduce_min_sync(~0u, cand);
                    int pr = t - 9;
                    if (pr >= 0) {
                        rv0[slot] = gvb[pr * K_ + lane];
                        rv1[slot] = (lane < 16) ? gvb[pr * K_ + 32 + lane] : 0.f;
                    }
                }
            }
        }
    }
}

extern "C" void kernel_launch(void* const* d_in, const int* in_sizes, int n_in,
                              void* d_out, int out_size) {
    const float* feats = (const float*)d_in[0];
    const float* trans = (const float*)d_in[1];
    const int*   tags  = (const int*)d_in[2];
    crf_kernel<<<B_, NT>>>(feats, trans, tags, (float*)d_out);
}